// round 16
// baseline (speedup 1.0000x reference)
#include <cuda_runtime.h>
#include <cstdint>

#define BATCH   8
#define TLEN    16384
#define NPOS    (BATCH*TLEN)     // 131072
#define RC      32
#define CIN     256
#define COUT    256
#define NLAYERS 40
#define TP      128              // positions per tile (MMA M)
#define TPB     4                // tiles per block
#define LGRID   (NPOS/(TP*TPB))  // 256

typedef unsigned int u32;
typedef unsigned long long u64;

// Persistent scratch, POSITION-major: h[pos][ch]
__device__ float g_h[2][(size_t)NPOS * RC];
__device__ float g_skip[(size_t)NPOS * RC];

// ---- smem byte offsets (single X buffer, 66KB total) ------------------------
#define XH_B    0                // 128 pos x 64 bf16, 144B pitch
#define XL_B    18432
#define W1H_B   36864            // 64 x 144
#define W1L_B   46080
#define W2H_B   55296            // 64 x 80
#define W2L_B   60416
#define SBIAS_B 65536
#define SMEM_BYTES 66048

// ---- helpers ---------------------------------------------------------------
__device__ __forceinline__ u32 pack_bf2(float lo, float hi) {
    u32 r; asm("cvt.rn.bf16x2.f32 %0, %1, %2;" : "=r"(r) : "f"(hi), "f"(lo)); return r;
}
__device__ __forceinline__ float bflo_f(u32 u) { return __uint_as_float(u << 16); }
__device__ __forceinline__ float bfhi_f(u32 u) { return __uint_as_float(u & 0xFFFF0000u); }

// non-volatile: pure register dataflow, ptxas may interleave independent chains
__device__ __forceinline__ void mma16816(float* c, const u32* a, u32 b0, u32 b1) {
    asm("mma.sync.aligned.m16n8k16.row.col.f32.bf16.bf16.f32 "
        "{%0,%1,%2,%3}, {%4,%5,%6,%7}, {%8,%9}, {%0,%1,%2,%3};"
        : "+f"(c[0]), "+f"(c[1]), "+f"(c[2]), "+f"(c[3])
        : "r"(a[0]), "r"(a[1]), "r"(a[2]), "r"(a[3]), "r"(b0), "r"(b1));
}

__device__ __forceinline__ void ldsm4(u32& r0, u32& r1, u32& r2, u32& r3, u32 addr) {
    asm volatile("ldmatrix.sync.aligned.m8n8.x4.shared.b16 {%0,%1,%2,%3}, [%4];"
        : "=r"(r0), "=r"(r1), "=r"(r2), "=r"(r3) : "r"(addr));
}

__device__ __forceinline__ void sts128(u32 addr, uint4 v) {
    asm volatile("st.shared.v4.b32 [%0], {%1,%2,%3,%4};"
        :: "r"(addr), "r"(v.x), "r"(v.y), "r"(v.z), "r"(v.w) : "memory");
}

__device__ __forceinline__ uint2 lds64(u32 addr) {
    uint2 v;
    asm volatile("ld.shared.v2.b32 {%0,%1}, [%2];"
        : "=r"(v.x), "=r"(v.y) : "r"(addr));
    return v;
}

__device__ __forceinline__ float htanh(float x) {
    float y; asm("tanh.approx.f32 %0, %1;" : "=f"(y) : "f"(x)); return y;
}
__device__ __forceinline__ float gated(float c, float g) {
    float t1 = htanh(c);
    float t2 = htanh(0.5f * g);
    float ht = 0.5f * t1;
    return fmaf(ht, t2, ht);
}

__device__ __forceinline__ u64 pack2f(float lo, float hi) {
    u64 r; asm("mov.b64 %0, {%1, %2};" : "=l"(r) : "f"(lo), "f"(hi)); return r;
}
__device__ __forceinline__ u64 dup2f(float x) {
    u64 r; asm("mov.b64 %0, {%1, %1};" : "=l"(r) : "f"(x)); return r;
}
__device__ __forceinline__ void unpack2f(u64 v, float& lo, float& hi) {
    asm("mov.b64 {%0, %1}, %2;" : "=f"(lo), "=f"(hi) : "l"(v));
}
#define FFMA2(d, a, b) asm("fma.rn.f32x2 %0, %1, %2, %0;" : "+l"(d) : "l"(a), "l"(b))

// load one position's X slice (16 channels) into regs; prev predicated by d
__device__ __forceinline__ void load_xslice(
    const float* __restrict__ hin, int pos, int half, int d,
    float4* pc, float4* pp)
{
    const float4* cp = (const float4*)(hin + (size_t)pos * RC + half * 16);
#pragma unroll
    for (int j = 0; j < 4; j++) pc[j] = __ldg(cp + j);
    bool hasp = ((pos & (TLEN - 1)) >= d);
    const float4* qp = (const float4*)(hin + (size_t)(pos - d) * RC + half * 16);
#pragma unroll
    for (int j = 0; j < 4; j++) {
        float4 z = make_float4(0.f, 0.f, 0.f, 0.f);
        if (hasp) z = __ldg(qp + j);
        pp[j] = z;
    }
}

// convert regs -> bf16 hi/lo rows and store (STS.128, conflict-free)
__device__ __forceinline__ void store_xslice(
    u32 hrow, u32 lrow, const float4* pc, const float4* pp)
{
#pragma unroll
    for (int cc = 0; cc < 4; cc++) {
        const float* c4 = (const float*)&pc[cc];
        const float* p4 = (const float*)&pp[cc];
        uint4 hi, lo;
        u32* hw = (u32*)&hi; u32* lw = (u32*)&lo;
#pragma unroll
        for (int m = 0; m < 4; m++) {
            u32 hp = pack_bf2(p4[m], c4[m]);     // k even = prev, k odd = cur
            hw[m] = hp;
            lw[m] = pack_bf2(p4[m] - bflo_f(hp), c4[m] - bfhi_f(hp));
        }
        sts128(hrow + cc*16, hi);
        sts128(lrow + cc*16, lo);
    }
}

// ---------------------------------------------------------------------------
// Input 1x1 conv: h[pos][ch] = in_w[32,256] @ x + in_b  (position-major out)
// ---------------------------------------------------------------------------
__global__ __launch_bounds__(256) void k_input(
    const float* __restrict__ x, const float* __restrict__ w,
    const float* __restrict__ b, float* __restrict__ hout)
{
    __shared__ float ws[CIN][RC];
    __shared__ float bs[RC];
    int tid = threadIdx.x;
    for (int idx = tid; idx < CIN * RC; idx += 256) {
        int o = idx / CIN, ic = idx % CIN;
        ws[ic][o] = w[idx];
    }
    if (tid < RC) bs[tid] = b[tid];
    __syncthreads();

    int p  = blockIdx.x * 256 + tid;
    int bb = p >> 14;
    int t  = p & (TLEN - 1);
    const float* xp = x + ((size_t)bb * CIN) * TLEN + t;

    u64 acc[16];
#pragma unroll
    for (int q = 0; q < 16; q++) acc[q] = pack2f(bs[2*q], bs[2*q+1]);

#pragma unroll 4
    for (int ic = 0; ic < CIN; ic++) {
        float xv = __ldg(xp + (size_t)ic * TLEN);
        u64 xd = dup2f(xv);
        const ulonglong2* wp = (const ulonglong2*)ws[ic];
#pragma unroll
        for (int q = 0; q < 8; q++) {
            ulonglong2 wv = wp[q];
            FFMA2(acc[2*q],   wv.x, xd);
            FFMA2(acc[2*q+1], wv.y, xd);
        }
    }
    float* hp = hout + (size_t)p * RC;
#pragma unroll
    for (int q = 0; q < 8; q++) {
        float4 v;
        unpack2f(acc[2*q],   v.x, v.y);
        unpack2f(acc[2*q+1], v.z, v.w);
        ((float4*)hp)[q] = v;
    }
}

// ---------------------------------------------------------------------------
// Residual layer: HMMA + ldmatrix, warp-autonomous tiles (NO block barriers
// in the tile loop). Each warp stages/computes/writes its own 16 rows.
// ---------------------------------------------------------------------------
__global__ __launch_bounds__(256) void k_layer(
    const float* __restrict__ hin, float* __restrict__ hout,
    float* __restrict__ skip,
    const float* __restrict__ cw, const float* __restrict__ cb,
    const float* __restrict__ gw, const float* __restrict__ gb,
    const float* __restrict__ rw, const float* __restrict__ rb,
    const float* __restrict__ sw, const float* __restrict__ sb,
    int d, int first)
{
    extern __shared__ u32 smem_u[];
    u32 smbase = (u32)__cvta_generic_to_shared(smem_u);

    int tid  = threadIdx.x;
    int wid  = tid >> 5, lane = tid & 31;
    int g    = lane >> 2, tig = lane & 3;
    int rin  = lane >> 1, half = lane & 1;     // row-in-warp, channel half
    int myrow = wid * 16 + rin;                // global row this lane stages

    // ---- stage weights once per block (row-major bf16 hi/lo) ----
    {
        int o = tid >> 2, q = tid & 3;
        const float* s1 = (o < 32 ? cw + (size_t)o * 64 : gw + (size_t)(o - 32) * 64) + q * 16;
        float v[16];
#pragma unroll
        for (int j = 0; j < 4; j++) *(float4*)(v + 4*j) = __ldg((const float4*)s1 + j);
        u32 hrow = smbase + W1H_B + (u32)o * 144 + (u32)q * 32;
        u32 lrow = smbase + W1L_B + (u32)o * 144 + (u32)q * 32;
#pragma unroll
        for (int cc = 0; cc < 2; cc++) {
            uint4 hi, lo;
            u32* hw = (u32*)&hi; u32* lw = (u32*)&lo;
#pragma unroll
            for (int m = 0; m < 4; m++) {
                float e = v[8*cc + 2*m], f = v[8*cc + 2*m + 1];
                u32 hp = pack_bf2(e, f);
                hw[m] = hp;
                lw[m] = pack_bf2(e - bflo_f(hp), f - bfhi_f(hp));
            }
            sts128(hrow + cc*16, hi);
            sts128(lrow + cc*16, lo);
        }
        const float* s2 = (o < 32 ? rw + (size_t)o * 32 : sw + (size_t)(o - 32) * 32) + q * 8;
        float v2[8];
#pragma unroll
        for (int j = 0; j < 2; j++) *(float4*)(v2 + 4*j) = __ldg((const float4*)s2 + j);
        uint4 hi2, lo2;
        u32* hw2 = (u32*)&hi2; u32* lw2 = (u32*)&lo2;
#pragma unroll
        for (int m = 0; m < 4; m++) {
            float e = v2[2*m], f = v2[2*m + 1];
            u32 hp = pack_bf2(e, f);
            hw2[m] = hp;
            lw2[m] = pack_bf2(e - bflo_f(hp), f - bfhi_f(hp));
        }
        sts128(smbase + W2H_B + (u32)o * 80 + (u32)q * 16, hi2);
        sts128(smbase + W2L_B + (u32)o * 80 + (u32)q * 16, lo2);
    }
    if (tid < 128) {
        float bv = (tid < 32) ? __ldg(cb + tid)
                 : (tid < 64) ? __ldg(gb + tid - 32)
                 : (tid < 96) ? __ldg(rb + tid - 64)
                              : __ldg(sb + tid - 96);
        smem_u[SBIAS_B/4 + tid] = __float_as_uint(bv);
    }
    __syncthreads();                    // weights visible to all; ONLY block barrier
    const float* sbias = (const float*)(smem_u + SBIAS_B/4);

    int blkbase = blockIdx.x * (TP * TPB);
    u32 stageRow = smbase + XH_B + (u32)myrow * 144 + (u32)half * 64;

    // ldmatrix lane-relative offsets
    u32 aAddr  = smbase + XH_B + (u32)(wid*16 + (lane & 15)) * 144 + (u32)(lane >> 4) * 16;
    u32 b1Addr = smbase + W1H_B + (u32)(lane & 7) * 144 + (u32)(lane >> 3) * 16;
    u32 b2Addr = smbase + W2H_B + (u32)(lane & 7) * 80  + (u32)(lane >> 3) * 16;

    // prefetch tile 0
    float4 pc[4], pp[4];
    load_xslice(hin, blkbase + myrow, half, d, pc, pp);

    for (int tt = 0; tt < TPB; tt++) {
        int base = blkbase + tt * TP;

        // ---- stage this warp's 16 rows (own region, warp-local sync) ----
        store_xslice(stageRow, stageRow + (XL_B - XH_B), pc, pp);
        __syncwarp();

        // ---- prefetch next tile's X into regs (hidden under GEMMs) ----
        if (tt + 1 < TPB)
            load_xslice(hin, base + TP + myrow, half, d, pc, pp);

        // ---- prefetch old skip values for writeback ----
        float2 skpf[8];
        if (!first) {
#pragma unroll
            for (int nt = 0; nt < 4; nt++) {
#pragma unroll
                for (int rr = 0; rr < 2; rr++) {
                    int pos = base + wid * 16 + g + rr * 8;
                    skpf[nt*2 + rr] = __ldg(
                        (const float2*)(skip + (size_t)pos * RC + nt*8 + 2*tig));
                }
            }
        }

        // ---- GEMM1: D1[16,64] per warp = X*W1^T (hi*hi + lo*hi + hi*lo) ----
        float acc1[8][4];
#pragma unroll
        for (int nt = 0; nt < 8; nt++) {
            float2 bv = *(const float2*)&sbias[nt*8 + 2*tig];
            acc1[nt][0] = bv.x; acc1[nt][1] = bv.y;
            acc1[nt][2] = bv.x; acc1[nt][3] = bv.y;
        }
#pragma unroll
        for (int kg = 0; kg < 2; kg++) {
            u32 ah0[4], al0[4], ah1[4], al1[4];
            ldsm4(ah0[0], ah0[1], ah0[2], ah0[3], aAddr + kg*64);
            ldsm4(ah1[0], ah1[1], ah1[2], ah1[3], aAddr + kg*64 + 32);
            ldsm4(al0[0], al0[1], al0[2], al0[3], aAddr + (XL_B - XH_B) + kg*64);
            ldsm4(al1[0], al1[1], al1[2], al1[3], aAddr + (XL_B - XH_B) + kg*64 + 32);
#pragma unroll
            for (int nt = 0; nt < 8; nt++) {
                uint4 bh, bl;
                ldsm4(bh.x, bh.y, bh.z, bh.w, b1Addr + (u32)nt*1152 + kg*64);
                ldsm4(bl.x, bl.y, bl.z, bl.w, b1Addr + (W1L_B - W1H_B) + (u32)nt*1152 + kg*64);
                mma16816(acc1[nt], ah0, bh.x, bh.y);
                mma16816(acc1[nt], al0, bh.x, bh.y);
                mma16816(acc1[nt], ah0, bl.x, bl.y);
                mma16816(acc1[nt], ah1, bh.z, bh.w);
                mma16816(acc1[nt], al1, bh.z, bh.w);
                mma16816(acc1[nt], ah1, bl.z, bl.w);
            }
        }

        // ---- gated activation -> GEMM2 A fragments (registers only) ----
        u32 a2h[2][4], a2l[2][4];
#pragma unroll
        for (int nt = 0; nt < 4; nt++) {
            float f0 = gated(acc1[nt][0], acc1[nt + 4][0]);
            float f1 = gated(acc1[nt][1], acc1[nt + 4][1]);
            float f2 = gated(acc1[nt][2], acc1[nt + 4][2]);
            float f3 = gated(acc1[nt][3], acc1[nt + 4][3]);
            int ks2 = nt >> 1, off = (nt & 1) * 2;
            u32 h0 = pack_bf2(f0, f1);
            u32 h1 = pack_bf2(f2, f3);
            a2h[ks2][off]     = h0;
            a2h[ks2][off + 1] = h1;
            a2l[ks2][off]     = pack_bf2(f0 - bflo_f(h0), f1 - bfhi_f(h0));
            a2l[ks2][off + 1] = pack_bf2(f2 - bflo_f(h1), f3 - bfhi_f(h1));
        }

        // ---- GEMM2: D2[16,64] per warp = A*W2^T ----
        float acc2[8][4];
#pragma unroll
        for (int nt = 0; nt < 8; nt++) {
            float2 bv = *(const float2*)&sbias[64 + nt*8 + 2*tig];
            acc2[nt][0] = bv.x; acc2[nt][1] = bv.y;
            acc2[nt][2] = bv.x; acc2[nt][3] = bv.y;
        }
#pragma unroll
        for (int nt = 0; nt < 8; nt++) {
            uint4 bh, bl;
            ldsm4(bh.x, bh.y, bh.z, bh.w, b2Addr + (u32)nt*640);
            ldsm4(bl.x, bl.y, bl.z, bl.w, b2Addr + (W2L_B - W2H_B) + (u32)nt*640);
            mma16816(acc2[nt], a2h[0], bh.x, bh.y);
            mma16816(acc2[nt], a2l[0], bh.x, bh.y);
            mma16816(acc2[nt], a2h[0], bl.x, bl.y);
            mma16816(acc2[nt], a2h[1], bh.z, bh.w);
            mma16816(acc2[nt], a2l[1], bh.z, bh.w);
            mma16816(acc2[nt], a2h[1], bl.z, bl.w);
        }

        // ---- writeback: hout = h(recon from smem) + res, skip = pf + s ----
#pragma unroll
        for (int nt = 0; nt < 4; nt++) {
            int ch = nt * 8 + 2 * tig;
#pragma unroll
            for (int rr = 0; rr < 2; rr++) {
                int row = wid * 16 + g + rr * 8;
                int pos = base + row;
                size_t idx = (size_t)pos * RC + ch;
                u32 off = smbase + XH_B + (u32)row * 144 + (u32)ch * 4;
                uint2 h2 = lds64(off);
                uint2 l2 = lds64(off + (XL_B - XH_B));
                float hc0 = bfhi_f(h2.x) + bfhi_f(l2.x);
                float hc1 = bfhi_f(h2.y) + bfhi_f(l2.y);
                float r0 = acc2[nt][rr*2], r1 = acc2[nt][rr*2 + 1];
                float s0 = acc2[nt + 4][rr*2], s1 = acc2[nt + 4][rr*2 + 1];
                if (!first) {
                    float2 os = skpf[nt*2 + rr];
                    s0 += os.x; s1 += os.y;
                }
                *(float2*)(hout + idx) = make_float2(hc0 + r0, hc1 + r1);
                *(float2*)(skip + idx) = make_float2(s0, s1);
            }
        }
        __syncwarp();   // own rows fully read before next tile's staging stores
    }
}

// ---------------------------------------------------------------------------
// Output head: out = s2( relu(s1(skip)) ), skip position-major, out [B][256][T]
// ---------------------------------------------------------------------------
__global__ __launch_bounds__(256) void k_final(
    const float* __restrict__ skip,
    const float* __restrict__ w1, const float* __restrict__ b1,
    const float* __restrict__ w2, const float* __restrict__ b2,
    float* __restrict__ out)
{
    __shared__ float ws1[RC * RC];
    __shared__ float ws2t[RC][COUT];
    __shared__ float bs1[RC];
    __shared__ float bs2[COUT];
    int tid = threadIdx.x;
    for (int idx = tid; idx < RC * RC; idx += 256) ws1[idx] = w1[idx];
    for (int idx = tid; idx < COUT * RC; idx += 256) {
        int o = idx / RC, i = idx % RC;
        ws2t[i][o] = w2[idx];
    }
    if (tid < RC) bs1[tid] = b1[tid];
    if (tid < COUT) bs2[tid] = b2[tid];
    __syncthreads();

    int p  = blockIdx.x * 256 + tid;
    int bb = p >> 14;
    int t  = p & (TLEN - 1);

    float sk[RC];
    const float4* sp = (const float4*)(skip + (size_t)p * RC);
#pragma unroll
    for (int q = 0; q < 8; q++) *(float4*)(sk + 4*q) = __ldg(sp + q);

    float u[RC];
#pragma unroll
    for (int o = 0; o < RC; o++) {
        float acc = bs1[o];
#pragma unroll
        for (int i = 0; i < RC; i++) acc = fmaf(ws1[o * RC + i], sk[i], acc);
        u[o] = fmaxf(acc, 0.0f);
    }

    float* op = out + ((size_t)bb * COUT) * TLEN + t;
    for (int og = 0; og < COUT / 16; og++) {
        int o0 = og * 16;
        u64 acc[8];
#pragma unroll
        for (int q = 0; q < 8; q++) acc[q] = pack2f(bs2[o0 + 2*q], bs2[o0 + 2*q + 1]);
#pragma unroll 8
        for (int i = 0; i < RC; i++) {
            u64 ud = dup2f(u[i]);
            const ulonglong2* wp = (const ulonglong2*)&ws2t[i][o0];
#pragma unroll
            for (int q2 = 0; q2 < 4; q2++) {
                ulonglong2 wv = wp[q2];
                FFMA2(acc[2*q2],   wv.x, ud);
                FFMA2(acc[2*q2+1], wv.y, ud);
            }
        }
#pragma unroll
        for (int q = 0; q < 8; q++) {
            float v0, v1;
            unpack2f(acc[q], v0, v1);
            op[(size_t)(o0 + 2*q)     * TLEN] = v0;
            op[(size_t)(o0 + 2*q + 1) * TLEN] = v1;
        }
    }
}

// ---------------------------------------------------------------------------
extern "C" void kernel_launch(void* const* d_in, const int* in_sizes, int n_in,
                              void* d_out, int out_size)
{
    const float* x      = (const float*)d_in[0];
    const float* in_w   = (const float*)d_in[1];
    const float* in_b   = (const float*)d_in[2];
    const float* conv_w = (const float*)d_in[3];
    const float* conv_b = (const float*)d_in[4];
    const float* gate_w = (const float*)d_in[5];
    const float* gate_b = (const float*)d_in[6];
    const float* res_w  = (const float*)d_in[7];
    const float* res_b  = (const float*)d_in[8];
    const float* skip_w = (const float*)d_in[9];
    const float* skip_b = (const float*)d_in[10];
    const float* s1_w   = (const float*)d_in[11];
    const float* s1_b   = (const float*)d_in[12];
    const float* s2_w   = (const float*)d_in[13];
    const float* s2_b   = (const float*)d_in[14];
    float* out = (float*)d_out;

    float* hbase = nullptr;
    float* skp   = nullptr;
    cudaGetSymbolAddress((void**)&hbase, g_h);
    cudaGetSymbolAddress((void**)&skp, g_skip);

    cudaFuncSetAttribute(k_layer, cudaFuncAttributeMaxDynamicSharedMemorySize, SMEM_BYTES);

    k_input<<<NPOS/256, 256>>>(x, in_w, in_b, hbase);

    int cur = 0;
    for (int i = 0; i < NLAYERS; i++) {
        int dd = 1 << (i % 10);
        const float* hin = hbase + (size_t)cur * NPOS * RC;
        float* hout      = hbase + (size_t)(cur ^ 1) * NPOS * RC;
        k_layer<<<LGRID, 256, SMEM_BYTES>>>(hin, hout, skp,
                                conv_w + (size_t)i * RC * RC * 2, conv_b + i * RC,
                                gate_w + (size_t)i * RC * RC * 2, gate_b + i * RC,
                                res_w  + (size_t)i * RC * RC,     res_b  + i * RC,
                                skip_w + (size_t)i * RC * RC,     skip_b + i * RC,
                                dd, (i == 0) ? 1 : 0);
        cur ^= 1;
    }

    k_final<<<NPOS/256, 256>>>(skp, s1_w, s1_b, s2_w, s2_b, out);
}

// round 17
// speedup vs baseline: 1.0020x; 1.0020x over previous
#include <cuda_runtime.h>
#include <cstdint>

#define BATCH   8
#define TLEN    16384
#define NPOS    (BATCH*TLEN)     // 131072
#define RC      32
#define CIN     256
#define COUT    256
#define NLAYERS 40
#define TP      128              // positions per tile (MMA M)
#define TPB     4                // tiles per block
#define LGRID   (NPOS/(TP*TPB))  // 256

typedef unsigned int u32;
typedef unsigned long long u64;

// Persistent scratch, POSITION-major: h[pos][ch]
__device__ float g_h[2][(size_t)NPOS * RC];
__device__ float g_skip[(size_t)NPOS * RC];

// ---- smem byte offsets (single X buffer, 66KB total) ------------------------
#define XH_B    0                // 128 pos x 64 bf16, 144B pitch
#define XL_B    18432
#define W1H_B   36864            // 64 x 144
#define W1L_B   46080
#define W2H_B   55296            // 64 x 80
#define W2L_B   60416
#define SBIAS_B 65536
#define SMEM_BYTES 66048

// ---- helpers ---------------------------------------------------------------
__device__ __forceinline__ u32 pack_bf2(float lo, float hi) {
    u32 r; asm("cvt.rn.bf16x2.f32 %0, %1, %2;" : "=r"(r) : "f"(hi), "f"(lo)); return r;
}
__device__ __forceinline__ float bflo_f(u32 u) { return __uint_as_float(u << 16); }
__device__ __forceinline__ float bfhi_f(u32 u) { return __uint_as_float(u & 0xFFFF0000u); }

// non-volatile: pure register dataflow, ptxas may interleave independent chains
__device__ __forceinline__ void mma16816(float* c, const u32* a, u32 b0, u32 b1) {
    asm("mma.sync.aligned.m16n8k16.row.col.f32.bf16.bf16.f32 "
        "{%0,%1,%2,%3}, {%4,%5,%6,%7}, {%8,%9}, {%0,%1,%2,%3};"
        : "+f"(c[0]), "+f"(c[1]), "+f"(c[2]), "+f"(c[3])
        : "r"(a[0]), "r"(a[1]), "r"(a[2]), "r"(a[3]), "r"(b0), "r"(b1));
}

__device__ __forceinline__ void ldsm4(u32& r0, u32& r1, u32& r2, u32& r3, u32 addr) {
    asm volatile("ldmatrix.sync.aligned.m8n8.x4.shared.b16 {%0,%1,%2,%3}, [%4];"
        : "=r"(r0), "=r"(r1), "=r"(r2), "=r"(r3) : "r"(addr));
}

__device__ __forceinline__ void sts128(u32 addr, uint4 v) {
    asm volatile("st.shared.v4.b32 [%0], {%1,%2,%3,%4};"
        :: "r"(addr), "r"(v.x), "r"(v.y), "r"(v.z), "r"(v.w) : "memory");
}

__device__ __forceinline__ uint2 lds64(u32 addr) {
    uint2 v;
    asm volatile("ld.shared.v2.b32 {%0,%1}, [%2];"
        : "=r"(v.x), "=r"(v.y) : "r"(addr));
    return v;
}

__device__ __forceinline__ float htanh(float x) {
    float y; asm("tanh.approx.f32 %0, %1;" : "=f"(y) : "f"(x)); return y;
}
__device__ __forceinline__ float gated(float c, float g) {
    float t1 = htanh(c);
    float t2 = htanh(0.5f * g);
    float ht = 0.5f * t1;
    return fmaf(ht, t2, ht);
}

__device__ __forceinline__ u64 pack2f(float lo, float hi) {
    u64 r; asm("mov.b64 %0, {%1, %2};" : "=l"(r) : "f"(lo), "f"(hi)); return r;
}
__device__ __forceinline__ u64 dup2f(float x) {
    u64 r; asm("mov.b64 %0, {%1, %1};" : "=l"(r) : "f"(x)); return r;
}
__device__ __forceinline__ void unpack2f(u64 v, float& lo, float& hi) {
    asm("mov.b64 {%0, %1}, %2;" : "=f"(lo), "=f"(hi) : "l"(v));
}
#define FFMA2(d, a, b) asm("fma.rn.f32x2 %0, %1, %2, %0;" : "+l"(d) : "l"(a), "l"(b))

// load one position's X slice (16 channels) into regs; prev predicated by d
__device__ __forceinline__ void load_xslice(
    const float* __restrict__ hin, int pos, int half, int d,
    float4* pc, float4* pp)
{
    const float4* cp = (const float4*)(hin + (size_t)pos * RC + half * 16);
#pragma unroll
    for (int j = 0; j < 4; j++) pc[j] = __ldg(cp + j);
    bool hasp = ((pos & (TLEN - 1)) >= d);
    const float4* qp = (const float4*)(hin + (size_t)(pos - d) * RC + half * 16);
#pragma unroll
    for (int j = 0; j < 4; j++) {
        float4 z = make_float4(0.f, 0.f, 0.f, 0.f);
        if (hasp) z = __ldg(qp + j);
        pp[j] = z;
    }
}

// convert regs -> bf16 hi/lo rows and store (STS.128, conflict-free)
__device__ __forceinline__ void store_xslice(
    u32 hrow, u32 lrow, const float4* pc, const float4* pp)
{
#pragma unroll
    for (int cc = 0; cc < 4; cc++) {
        const float* c4 = (const float*)&pc[cc];
        const float* p4 = (const float*)&pp[cc];
        uint4 hi, lo;
        u32* hw = (u32*)&hi; u32* lw = (u32*)&lo;
#pragma unroll
        for (int m = 0; m < 4; m++) {
            u32 hp = pack_bf2(p4[m], c4[m]);     // k even = prev, k odd = cur
            hw[m] = hp;
            lw[m] = pack_bf2(p4[m] - bflo_f(hp), c4[m] - bfhi_f(hp));
        }
        sts128(hrow + cc*16, hi);
        sts128(lrow + cc*16, lo);
    }
}

// ---------------------------------------------------------------------------
// Input 1x1 conv: h[pos][ch] = in_w[32,256] @ x + in_b  (position-major out)
// ---------------------------------------------------------------------------
__global__ __launch_bounds__(256) void k_input(
    const float* __restrict__ x, const float* __restrict__ w,
    const float* __restrict__ b, float* __restrict__ hout)
{
    __shared__ float ws[CIN][RC];
    __shared__ float bs[RC];
    int tid = threadIdx.x;
    for (int idx = tid; idx < CIN * RC; idx += 256) {
        int o = idx / CIN, ic = idx % CIN;
        ws[ic][o] = w[idx];
    }
    if (tid < RC) bs[tid] = b[tid];
    __syncthreads();

    int p  = blockIdx.x * 256 + tid;
    int bb = p >> 14;
    int t  = p & (TLEN - 1);
    const float* xp = x + ((size_t)bb * CIN) * TLEN + t;

    u64 acc[16];
#pragma unroll
    for (int q = 0; q < 16; q++) acc[q] = pack2f(bs[2*q], bs[2*q+1]);

#pragma unroll 4
    for (int ic = 0; ic < CIN; ic++) {
        float xv = __ldg(xp + (size_t)ic * TLEN);
        u64 xd = dup2f(xv);
        const ulonglong2* wp = (const ulonglong2*)ws[ic];
#pragma unroll
        for (int q = 0; q < 8; q++) {
            ulonglong2 wv = wp[q];
            FFMA2(acc[2*q],   wv.x, xd);
            FFMA2(acc[2*q+1], wv.y, xd);
        }
    }
    float* hp = hout + (size_t)p * RC;
#pragma unroll
    for (int q = 0; q < 8; q++) {
        float4 v;
        unpack2f(acc[2*q],   v.x, v.y);
        unpack2f(acc[2*q+1], v.z, v.w);
        ((float4*)hp)[q] = v;
    }
}

// ---------------------------------------------------------------------------
// Residual layer: HMMA + ldmatrix, warp-autonomous tiles (NO block barriers
// in the tile loop). Each warp stages/computes/writes its own 16 rows.
// ---------------------------------------------------------------------------
__global__ __launch_bounds__(256) void k_layer(
    const float* __restrict__ hin, float* __restrict__ hout,
    float* __restrict__ skip,
    const float* __restrict__ cw, const float* __restrict__ cb,
    const float* __restrict__ gw, const float* __restrict__ gb,
    const float* __restrict__ rw, const float* __restrict__ rb,
    const float* __restrict__ sw, const float* __restrict__ sb,
    int d, int first)
{
    extern __shared__ u32 smem_u[];
    u32 smbase = (u32)__cvta_generic_to_shared(smem_u);

    int tid  = threadIdx.x;
    int wid  = tid >> 5, lane = tid & 31;
    int g    = lane >> 2, tig = lane & 3;
    int rin  = lane >> 1, half = lane & 1;     // row-in-warp, channel half
    int myrow = wid * 16 + rin;                // global row this lane stages

    // ---- stage weights once per block (row-major bf16 hi/lo) ----
    {
        int o = tid >> 2, q = tid & 3;
        const float* s1 = (o < 32 ? cw + (size_t)o * 64 : gw + (size_t)(o - 32) * 64) + q * 16;
        float v[16];
#pragma unroll
        for (int j = 0; j < 4; j++) *(float4*)(v + 4*j) = __ldg((const float4*)s1 + j);
        u32 hrow = smbase + W1H_B + (u32)o * 144 + (u32)q * 32;
        u32 lrow = smbase + W1L_B + (u32)o * 144 + (u32)q * 32;
#pragma unroll
        for (int cc = 0; cc < 2; cc++) {
            uint4 hi, lo;
            u32* hw = (u32*)&hi; u32* lw = (u32*)&lo;
#pragma unroll
            for (int m = 0; m < 4; m++) {
                float e = v[8*cc + 2*m], f = v[8*cc + 2*m + 1];
                u32 hp = pack_bf2(e, f);
                hw[m] = hp;
                lw[m] = pack_bf2(e - bflo_f(hp), f - bfhi_f(hp));
            }
            sts128(hrow + cc*16, hi);
            sts128(lrow + cc*16, lo);
        }
        const float* s2 = (o < 32 ? rw + (size_t)o * 32 : sw + (size_t)(o - 32) * 32) + q * 8;
        float v2[8];
#pragma unroll
        for (int j = 0; j < 2; j++) *(float4*)(v2 + 4*j) = __ldg((const float4*)s2 + j);
        uint4 hi2, lo2;
        u32* hw2 = (u32*)&hi2; u32* lw2 = (u32*)&lo2;
#pragma unroll
        for (int m = 0; m < 4; m++) {
            float e = v2[2*m], f = v2[2*m + 1];
            u32 hp = pack_bf2(e, f);
            hw2[m] = hp;
            lw2[m] = pack_bf2(e - bflo_f(hp), f - bfhi_f(hp));
        }
        sts128(smbase + W2H_B + (u32)o * 80 + (u32)q * 16, hi2);
        sts128(smbase + W2L_B + (u32)o * 80 + (u32)q * 16, lo2);
    }
    if (tid < 128) {
        float bv = (tid < 32) ? __ldg(cb + tid)
                 : (tid < 64) ? __ldg(gb + tid - 32)
                 : (tid < 96) ? __ldg(rb + tid - 64)
                              : __ldg(sb + tid - 96);
        smem_u[SBIAS_B/4 + tid] = __float_as_uint(bv);
    }
    __syncthreads();                    // weights visible to all; ONLY block barrier
    const float* sbias = (const float*)(smem_u + SBIAS_B/4);

    int blkbase = blockIdx.x * (TP * TPB);
    u32 stageRow = smbase + XH_B + (u32)myrow * 144 + (u32)half * 64;

    // ldmatrix lane-relative offsets
    u32 aAddr  = smbase + XH_B + (u32)(wid*16 + (lane & 15)) * 144 + (u32)(lane >> 4) * 16;
    u32 b1Addr = smbase + W1H_B + (u32)(lane & 7) * 144 + (u32)(lane >> 3) * 16;
    u32 b2Addr = smbase + W2H_B + (u32)(lane & 7) * 80  + (u32)(lane >> 3) * 16;

    // prefetch tile 0
    float4 pc[4], pp[4];
    load_xslice(hin, blkbase + myrow, half, d, pc, pp);

    for (int tt = 0; tt < TPB; tt++) {
        int base = blkbase + tt * TP;

        // ---- stage this warp's 16 rows (own region, warp-local sync) ----
        store_xslice(stageRow, stageRow + (XL_B - XH_B), pc, pp);
        __syncwarp();

        // ---- prefetch next tile's X into regs (hidden under GEMMs) ----
        if (tt + 1 < TPB)
            load_xslice(hin, base + TP + myrow, half, d, pc, pp);

        // ---- prefetch old skip values for writeback ----
        float2 skpf[8];
        if (!first) {
#pragma unroll
            for (int nt = 0; nt < 4; nt++) {
#pragma unroll
                for (int rr = 0; rr < 2; rr++) {
                    int pos = base + wid * 16 + g + rr * 8;
                    skpf[nt*2 + rr] = __ldg(
                        (const float2*)(skip + (size_t)pos * RC + nt*8 + 2*tig));
                }
            }
        }

        // ---- GEMM1: D1[16,64] per warp = X*W1^T (hi*hi + lo*hi + hi*lo) ----
        float acc1[8][4];
#pragma unroll
        for (int nt = 0; nt < 8; nt++) {
            float2 bv = *(const float2*)&sbias[nt*8 + 2*tig];
            acc1[nt][0] = bv.x; acc1[nt][1] = bv.y;
            acc1[nt][2] = bv.x; acc1[nt][3] = bv.y;
        }
#pragma unroll
        for (int kg = 0; kg < 2; kg++) {
            u32 ah0[4], al0[4], ah1[4], al1[4];
            ldsm4(ah0[0], ah0[1], ah0[2], ah0[3], aAddr + kg*64);
            ldsm4(ah1[0], ah1[1], ah1[2], ah1[3], aAddr + kg*64 + 32);
            ldsm4(al0[0], al0[1], al0[2], al0[3], aAddr + (XL_B - XH_B) + kg*64);
            ldsm4(al1[0], al1[1], al1[2], al1[3], aAddr + (XL_B - XH_B) + kg*64 + 32);
#pragma unroll
            for (int nt = 0; nt < 8; nt++) {
                uint4 bh, bl;
                ldsm4(bh.x, bh.y, bh.z, bh.w, b1Addr + (u32)nt*1152 + kg*64);
                ldsm4(bl.x, bl.y, bl.z, bl.w, b1Addr + (W1L_B - W1H_B) + (u32)nt*1152 + kg*64);
                mma16816(acc1[nt], ah0, bh.x, bh.y);
                mma16816(acc1[nt], al0, bh.x, bh.y);
                mma16816(acc1[nt], ah0, bl.x, bl.y);
                mma16816(acc1[nt], ah1, bh.z, bh.w);
                mma16816(acc1[nt], al1, bh.z, bh.w);
                mma16816(acc1[nt], ah1, bl.z, bl.w);
            }
        }

        // ---- gated activation -> GEMM2 A fragments (registers only) ----
        u32 a2h[2][4], a2l[2][4];
#pragma unroll
        for (int nt = 0; nt < 4; nt++) {
            float f0 = gated(acc1[nt][0], acc1[nt + 4][0]);
            float f1 = gated(acc1[nt][1], acc1[nt + 4][1]);
            float f2 = gated(acc1[nt][2], acc1[nt + 4][2]);
            float f3 = gated(acc1[nt][3], acc1[nt + 4][3]);
            int ks2 = nt >> 1, off = (nt & 1) * 2;
            u32 h0 = pack_bf2(f0, f1);
            u32 h1 = pack_bf2(f2, f3);
            a2h[ks2][off]     = h0;
            a2h[ks2][off + 1] = h1;
            a2l[ks2][off]     = pack_bf2(f0 - bflo_f(h0), f1 - bfhi_f(h0));
            a2l[ks2][off + 1] = pack_bf2(f2 - bflo_f(h1), f3 - bfhi_f(h1));
        }

        // ---- GEMM2: D2[16,64] per warp = A*W2^T ----
        float acc2[8][4];
#pragma unroll
        for (int nt = 0; nt < 8; nt++) {
            float2 bv = *(const float2*)&sbias[64 + nt*8 + 2*tig];
            acc2[nt][0] = bv.x; acc2[nt][1] = bv.y;
            acc2[nt][2] = bv.x; acc2[nt][3] = bv.y;
        }
#pragma unroll
        for (int nt = 0; nt < 8; nt++) {
            uint4 bh, bl;
            ldsm4(bh.x, bh.y, bh.z, bh.w, b2Addr + (u32)nt*640);
            ldsm4(bl.x, bl.y, bl.z, bl.w, b2Addr + (W2L_B - W2H_B) + (u32)nt*640);
            mma16816(acc2[nt], a2h[0], bh.x, bh.y);
            mma16816(acc2[nt], a2l[0], bh.x, bh.y);
            mma16816(acc2[nt], a2h[0], bl.x, bl.y);
            mma16816(acc2[nt], a2h[1], bh.z, bh.w);
            mma16816(acc2[nt], a2l[1], bh.z, bh.w);
            mma16816(acc2[nt], a2h[1], bl.z, bl.w);
        }

        // ---- writeback: hout = h(recon from smem) + res, skip = pf + s ----
#pragma unroll
        for (int nt = 0; nt < 4; nt++) {
            int ch = nt * 8 + 2 * tig;
#pragma unroll
            for (int rr = 0; rr < 2; rr++) {
                int row = wid * 16 + g + rr * 8;
                int pos = base + row;
                size_t idx = (size_t)pos * RC + ch;
                u32 off = smbase + XH_B + (u32)row * 144 + (u32)ch * 4;
                uint2 h2 = lds64(off);
                uint2 l2 = lds64(off + (XL_B - XH_B));
                float hc0 = bfhi_f(h2.x) + bfhi_f(l2.x);
                float hc1 = bfhi_f(h2.y) + bfhi_f(l2.y);
                float r0 = acc2[nt][rr*2], r1 = acc2[nt][rr*2 + 1];
                float s0 = acc2[nt + 4][rr*2], s1 = acc2[nt + 4][rr*2 + 1];
                if (!first) {
                    float2 os = skpf[nt*2 + rr];
                    s0 += os.x; s1 += os.y;
                }
                *(float2*)(hout + idx) = make_float2(hc0 + r0, hc1 + r1);
                *(float2*)(skip + idx) = make_float2(s0, s1);
            }
        }
        __syncwarp();   // own rows fully read before next tile's staging stores
    }
}

// ---------------------------------------------------------------------------
// Output head: out = s2( relu(s1(skip)) ), skip position-major, out [B][256][T]
// ---------------------------------------------------------------------------
__global__ __launch_bounds__(256) void k_final(
    const float* __restrict__ skip,
    const float* __restrict__ w1, const float* __restrict__ b1,
    const float* __restrict__ w2, const float* __restrict__ b2,
    float* __restrict__ out)
{
    __shared__ float ws1[RC * RC];
    __shared__ float ws2t[RC][COUT];
    __shared__ float bs1[RC];
    __shared__ float bs2[COUT];
    int tid = threadIdx.x;
    for (int idx = tid; idx < RC * RC; idx += 256) ws1[idx] = w1[idx];
    for (int idx = tid; idx < COUT * RC; idx += 256) {
        int o = idx / RC, i = idx % RC;
        ws2t[i][o] = w2[idx];
    }
    if (tid < RC) bs1[tid] = b1[tid];
    if (tid < COUT) bs2[tid] = b2[tid];
    __syncthreads();

    int p  = blockIdx.x * 256 + tid;
    int bb = p >> 14;
    int t  = p & (TLEN - 1);

    float sk[RC];
    const float4* sp = (const float4*)(skip + (size_t)p * RC);
#pragma unroll
    for (int q = 0; q < 8; q++) *(float4*)(sk + 4*q) = __ldg(sp + q);

    float u[RC];
#pragma unroll
    for (int o = 0; o < RC; o++) {
        float acc = bs1[o];
#pragma unroll
        for (int i = 0; i < RC; i++) acc = fmaf(ws1[o * RC + i], sk[i], acc);
        u[o] = fmaxf(acc, 0.0f);
    }

    float* op = out + ((size_t)bb * COUT) * TLEN + t;
    for (int og = 0; og < COUT / 16; og++) {
        int o0 = og * 16;
        u64 acc[8];
#pragma unroll
        for (int q = 0; q < 8; q++) acc[q] = pack2f(bs2[o0 + 2*q], bs2[o0 + 2*q + 1]);
#pragma unroll 8
        for (int i = 0; i < RC; i++) {
            u64 ud = dup2f(u[i]);
            const ulonglong2* wp = (const ulonglong2*)&ws2t[i][o0];
#pragma unroll
            for (int q2 = 0; q2 < 4; q2++) {
                ulonglong2 wv = wp[q2];
                FFMA2(acc[2*q2],   wv.x, ud);
                FFMA2(acc[2*q2+1], wv.y, ud);
            }
        }
#pragma unroll
        for (int q = 0; q < 8; q++) {
            float v0, v1;
            unpack2f(acc[q], v0, v1);
            op[(size_t)(o0 + 2*q)     * TLEN] = v0;
            op[(size_t)(o0 + 2*q + 1) * TLEN] = v1;
        }
    }
}

// ---------------------------------------------------------------------------
extern "C" void kernel_launch(void* const* d_in, const int* in_sizes, int n_in,
                              void* d_out, int out_size)
{
    const float* x      = (const float*)d_in[0];
    const float* in_w   = (const float*)d_in[1];
    const float* in_b   = (const float*)d_in[2];
    const float* conv_w = (const float*)d_in[3];
    const float* conv_b = (const float*)d_in[4];
    const float* gate_w = (const float*)d_in[5];
    const float* gate_b = (const float*)d_in[6];
    const float* res_w  = (const float*)d_in[7];
    const float* res_b  = (const float*)d_in[8];
    const float* skip_w = (const float*)d_in[9];
    const float* skip_b = (const float*)d_in[10];
    const float* s1_w   = (const float*)d_in[11];
    const float* s1_b   = (const float*)d_in[12];
    const float* s2_w   = (const float*)d_in[13];
    const float* s2_b   = (const float*)d_in[14];
    float* out = (float*)d_out;

    float* hbase = nullptr;
    float* skp   = nullptr;
    cudaGetSymbolAddress((void**)&hbase, g_h);
    cudaGetSymbolAddress((void**)&skp, g_skip);

    cudaFuncSetAttribute(k_layer, cudaFuncAttributeMaxDynamicSharedMemorySize, SMEM_BYTES);

    k_input<<<NPOS/256, 256>>>(x, in_w, in_b, hbase);

    int cur = 0;
    for (int i = 0; i < NLAYERS; i++) {
        int dd = 1 << (i % 10);
        const float* hin = hbase + (size_t)cur * NPOS * RC;
        float* hout      = hbase + (size_t)(cur ^ 1) * NPOS * RC;
        k_layer<<<LGRID, 256, SMEM_BYTES>>>(hin, hout, skp,
                                conv_w + (size_t)i * RC * RC * 2, conv_b + i * RC,
                                gate_w + (size_t)i * RC * RC * 2, gate_b + i * RC,
                                res_w  + (size_t)i * RC * RC,     res_b  + i * RC,
                                skip_w + (size_t)i * RC * RC,     skip_b + i * RC,
                                dd, (i == 0) ? 1 : 0);
        cur ^= 1;
    }

    k_final<<<NPOS/256, 256>>>(skp, s1_w, s1_b, s2_w, s2_b, out);
}